// round 17
// baseline (speedup 1.0000x reference)
#include <cuda_runtime.h>
#include <cuda_fp16.h>
#include <cstdint>

#define DEV_INLINE __device__ __forceinline__

// ------------------------------- helpers ----------------------------------
DEV_INLINE uint32_t smem_u32(const void* p) {
    uint32_t a;
    asm("{ .reg .u64 t; cvta.to.shared.u64 t, %1; cvt.u32.u64 %0, t; }"
        : "=r"(a) : "l"(p));
    return a;
}
DEV_INLINE void cpa16(uint32_t dst, const void* src) {
    asm volatile("cp.async.ca.shared.global [%0], [%1], 16;"
                 :: "r"(dst), "l"(src) : "memory");
}
DEV_INLINE void cpa_commit() {
    asm volatile("cp.async.commit_group;" ::: "memory");
}
template <int N>
DEV_INLINE void cpa_wait() {
    asm volatile("cp.async.wait_group %0;" :: "n"(N) : "memory");
}

DEV_INLINE void mma16816h(float* c, const uint32_t* a, const uint32_t* b) {
    asm volatile(
        "mma.sync.aligned.m16n8k16.row.col.f32.f16.f16.f32 "
        "{%0,%1,%2,%3}, {%4,%5,%6,%7}, {%8,%9}, {%0,%1,%2,%3};"
        : "+f"(c[0]), "+f"(c[1]), "+f"(c[2]), "+f"(c[3])
        : "r"(a[0]), "r"(a[1]), "r"(a[2]), "r"(a[3]), "r"(b[0]), "r"(b[1]));
}
DEV_INLINE void mma16808h(float* c, const uint32_t* a, uint32_t b) {
    asm volatile(
        "mma.sync.aligned.m16n8k8.row.col.f32.f16.f16.f32 "
        "{%0,%1,%2,%3}, {%4,%5}, {%6}, {%0,%1,%2,%3};"
        : "+f"(c[0]), "+f"(c[1]), "+f"(c[2]), "+f"(c[3])
        : "r"(a[0]), "r"(a[1]), "r"(b));
}
DEV_INLINE uint32_t packh(float lo, float hi) {  // low half = lo
    uint32_t r;
    asm("cvt.rn.f16x2.f32 %0, %1, %2;" : "=r"(r) : "f"(hi), "f"(lo));
    return r;
}

// ------------------------------- problem constants ------------------------
constexpr int Bc = 2, Pc = 2048, Hc = 8, DFc = 32;
constexpr float QSCALE = 0.17677669529663687f;  // 1/sqrt(32)

__device__ __align__(16) __half g_xh[Bc * Pc * 128];       // x fp16
__device__ __align__(16) __half g_wh[768 * 128];           // Wqkv fp16
__device__ __align__(16) __half g_wp[128 * 256];           // Wproj fp16
__device__ __align__(16) __half g_qh[Bc * 8 * Pc * 32];    // [b,h,p,d] scaled
__device__ __align__(16) __half g_kh[Bc * 8 * Pc * 32];    // [b,h,q,d]
__device__ __align__(16) __half g_vt[Bc * 8 * 32 * Pc];    // [b,h,d,q]
__device__ __align__(16) __half g_ctxt_h[Bc * Pc * 256];   // ctxt fp16
__device__ __align__(16) float g_oscr[2 * Bc * Pc * 256];  // [ks,b,p,256]
__device__ __align__(16) float2 g_mlscr[2 * Bc * 8 * Pc];  // [ks,b,g,p]

// ---------------------------------------------------------------------------
// fp32 -> fp16 conversion
// ---------------------------------------------------------------------------
__global__ __launch_bounds__(256) void cvt_f2h(const float* __restrict__ src,
                                               __half* __restrict__ dst, int n4) {
    int i = blockIdx.x * 256 + threadIdx.x;
    if (i < n4) {
        float4 v = ((const float4*)src)[i];
        __half2* d = (__half2*)dst + i * 2;
        d[0] = __floats2half2_rn(v.x, v.y);
        d[1] = __floats2half2_rn(v.z, v.w);
    }
}

// ---------------------------------------------------------------------------
// QKV projection on tensor pipe: qkv = x @ Wqkv^T, scatter epilogue.
// ---------------------------------------------------------------------------
DEV_INLINE void scatter_qkv(int r, int c, float val) {
    int bb = r >> 11, p = r & 2047;
    int sgrp = c >> 8, h = (c >> 5) & 7, d = c & 31;
    size_t hp = ((size_t)(bb * 8 + h) * Pc + p) * 32 + d;
    if (sgrp == 0)      g_qh[hp] = __float2half_rn(val * QSCALE);
    else if (sgrp == 1) g_kh[hp] = __float2half_rn(val);
    else g_vt[((size_t)(bb * 8 + h) * 32 + d) * Pc + p] = __float2half_rn(val);
}

__global__ __launch_bounds__(256, 2) void gemm_qkv_h() {
    __shared__ __align__(16) __half As[128][136];
    __shared__ __align__(16) __half Bs[64][136];

    const int tid = threadIdx.x;
    const int w = tid >> 5, lane = tid & 31;
    const int la = lane >> 2, lb = lane & 3;
    const int wm = w >> 1, wn = w & 1;
    const int m0 = blockIdx.x << 7, n0 = blockIdx.y << 6;

#pragma unroll
    for (int i = 0; i < 8; i++) {
        int idx = tid + (i << 8);
        int row = idx >> 4, c16 = idx & 15;
        *(uint4*)&As[row][c16 * 8] =
            *(const uint4*)(g_xh + (size_t)(m0 + row) * 128 + c16 * 8);
    }
#pragma unroll
    for (int i = 0; i < 4; i++) {
        int idx = tid + (i << 8);
        int row = idx >> 4, c16 = idx & 15;
        *(uint4*)&Bs[row][c16 * 8] =
            *(const uint4*)(g_wh + (size_t)(n0 + row) * 128 + c16 * 8);
    }
    __syncthreads();

    float c[2][4][4];
#pragma unroll
    for (int mt = 0; mt < 2; mt++)
#pragma unroll
        for (int nt = 0; nt < 4; nt++)
#pragma unroll
            for (int i = 0; i < 4; i++) c[mt][nt][i] = 0.f;

#pragma unroll
    for (int ks = 0; ks < 8; ks++) {
#pragma unroll
        for (int mt = 0; mt < 2; mt++) {
            uint32_t a[4];
            const __half* ab = &As[wm * 32 + 16 * mt + la][ks * 16 + 2 * lb];
            a[0] = *(const uint32_t*)(ab);
            a[1] = *(const uint32_t*)(ab + 8 * 136);
            a[2] = *(const uint32_t*)(ab + 8);
            a[3] = *(const uint32_t*)(ab + 8 * 136 + 8);
#pragma unroll
            for (int nt = 0; nt < 4; nt++) {
                uint32_t bb[2];
                const __half* bbp = &Bs[wn * 32 + 8 * nt + la][ks * 16 + 2 * lb];
                bb[0] = *(const uint32_t*)(bbp);
                bb[1] = *(const uint32_t*)(bbp + 8);
                mma16816h(c[mt][nt], a, bb);
            }
        }
    }

#pragma unroll
    for (int mt = 0; mt < 2; mt++)
#pragma unroll
        for (int nt = 0; nt < 4; nt++) {
            int r = m0 + wm * 32 + 16 * mt + la;
            int cc = n0 + wn * 32 + 8 * nt + 2 * lb;
            scatter_qkv(r,     cc,     c[mt][nt][0]);
            scatter_qkv(r,     cc + 1, c[mt][nt][1]);
            scatter_qkv(r + 8, cc,     c[mt][nt][2]);
            scatter_qkv(r + 8, cc + 1, c[mt][nt][3]);
        }
}

// ---------------------------------------------------------------------------
// Output projection on tensor pipe: out = ctxt_h @ Wproj^T
// ---------------------------------------------------------------------------
__global__ __launch_bounds__(256, 2) void gemm_proj(float* __restrict__ out) {
    __shared__ __align__(16) __half As[128][136];
    __shared__ __align__(16) __half Bs[64][136];

    const int tid = threadIdx.x;
    const int w = tid >> 5, lane = tid & 31;
    const int la = lane >> 2, lb = lane & 3;
    const int wm = w >> 1, wn = w & 1;
    const int m0 = blockIdx.x << 7, n0 = blockIdx.y << 6;

    float c[2][4][4];
#pragma unroll
    for (int mt = 0; mt < 2; mt++)
#pragma unroll
        for (int nt = 0; nt < 4; nt++)
#pragma unroll
            for (int i = 0; i < 4; i++) c[mt][nt][i] = 0.f;

    for (int kc = 0; kc < 256; kc += 128) {
        if (kc) __syncthreads();
#pragma unroll
        for (int i = 0; i < 8; i++) {
            int idx = tid + (i << 8);
            int row = idx >> 4, c16 = idx & 15;
            *(uint4*)&As[row][c16 * 8] =
                *(const uint4*)(g_ctxt_h + (size_t)(m0 + row) * 256 + kc + c16 * 8);
        }
#pragma unroll
        for (int i = 0; i < 4; i++) {
            int idx = tid + (i << 8);
            int row = idx >> 4, c16 = idx & 15;
            *(uint4*)&Bs[row][c16 * 8] =
                *(const uint4*)(g_wp + (size_t)(n0 + row) * 256 + kc + c16 * 8);
        }
        __syncthreads();

#pragma unroll
        for (int ks = 0; ks < 8; ks++) {
#pragma unroll
            for (int mt = 0; mt < 2; mt++) {
                uint32_t a[4];
                const __half* ab = &As[wm * 32 + 16 * mt + la][ks * 16 + 2 * lb];
                a[0] = *(const uint32_t*)(ab);
                a[1] = *(const uint32_t*)(ab + 8 * 136);
                a[2] = *(const uint32_t*)(ab + 8);
                a[3] = *(const uint32_t*)(ab + 8 * 136 + 8);
#pragma unroll
                for (int nt = 0; nt < 4; nt++) {
                    uint32_t bb[2];
                    const __half* bbp = &Bs[wn * 32 + 8 * nt + la][ks * 16 + 2 * lb];
                    bb[0] = *(const uint32_t*)(bbp);
                    bb[1] = *(const uint32_t*)(bbp + 8);
                    mma16816h(c[mt][nt], a, bb);
                }
            }
        }
    }

#pragma unroll
    for (int mt = 0; mt < 2; mt++)
#pragma unroll
        for (int nt = 0; nt < 4; nt++) {
            int r = m0 + wm * 32 + 16 * mt + la;
            int cc = n0 + wn * 32 + 8 * nt + 2 * lb;
            *(float2*)(out + (size_t)r * 128 + cc) =
                make_float2(c[mt][nt][0], c[mt][nt][1]);
            *(float2*)(out + (size_t)(r + 8) * 128 + cc) =
                make_float2(c[mt][nt][2], c[mt][nt][3]);
        }
}

// ---------------------------------------------------------------------------
// Fused talking-heads attention: pipelined cp.async (K double-buffered),
// T in fp16. Layout audits in comments.
// ---------------------------------------------------------------------------
constexpr int K0_OFF = 0;              // K buf0 [h*32+q] rows 80B -> 20480
constexpr int K1_OFF = 20480;          // K buf1                    -> 20480
constexpr int V_OFF = 40960;           // [g*32+d] rows 80B         -> 20480
constexpr int S_OFF = 61440;           // [p]516B,[q]16B,[h]2B      -> 16512
constexpr int T_OFF = 77952;           // fp16: [g]2576B,[p]80B     -> 20608
constexpr int SM_ATTN = 98560;

__global__ __launch_bounds__(256, 2) void attn_mma(const float* __restrict__ bias,
                                                   const float* __restrict__ wtalk) {
    extern __shared__ char smem[];
    const uint32_t sb = smem_u32(smem);

    const int tid = threadIdx.x;
    const int w = tid >> 5, lane = tid & 31;
    const int la = lane >> 2, lb = lane & 3;
    const int b = blockIdx.x & 1;
    const int ks = (blockIdx.x >> 1) & 1;
    const int p0 = (blockIdx.x >> 2) << 5;

    const __half* kb = g_kh + (size_t)(b * 8) * Pc * 32;
    const __half* vb = g_vt + (size_t)(b * 8) * 32 * Pc;

    uint32_t qf[2][2][4];
    {
        const __half* qb = g_qh + ((size_t)(b * 8 + w) * Pc + p0) * 32;
#pragma unroll
        for (int mt = 0; mt < 2; mt++)
#pragma unroll
            for (int k2 = 0; k2 < 2; k2++) {
                int d = 16 * k2 + 2 * lb;
                qf[mt][k2][0] = *(const uint32_t*)(qb + (16 * mt + la) * 32 + d);
                qf[mt][k2][1] = *(const uint32_t*)(qb + (16 * mt + la + 8) * 32 + d);
                qf[mt][k2][2] = *(const uint32_t*)(qb + (16 * mt + la) * 32 + d + 8);
                qf[mt][k2][3] = *(const uint32_t*)(qb + (16 * mt + la + 8) * 32 + d + 8);
            }
    }
    const uint32_t wfrag =
        packh(wtalk[la * 8 + 2 * lb], wtalk[la * 8 + 2 * lb + 1]);

    float o[2][4][4];
#pragma unroll
    for (int mt = 0; mt < 2; mt++)
#pragma unroll
        for (int nt = 0; nt < 4; nt++)
#pragma unroll
            for (int i = 0; i < 4; i++) o[mt][nt][i] = 0.f;
    float mr[2][2], lr[2][2];
#pragma unroll
    for (int mt = 0; mt < 2; mt++) {
        mr[mt][0] = -1e30f; mr[mt][1] = -1e30f;
        lr[mt][0] = 0.f;    lr[mt][1] = 0.f;
    }

    // K staging coords (per thread): head tid>>5, row tid&31
    const __half* ksrc_base = kb + ((size_t)(tid >> 5) * Pc + (tid & 31)) * 32;
    const __half* vsrc_base = vb + (size_t)tid * Pc;

    // ---- prologue: prefetch K(0) into buf0 ----
    {
        const __half* srcK = ksrc_base + (size_t)(ks * 32) * 32;
        uint32_t dstK = sb + K0_OFF + tid * 80;
#pragma unroll
        for (int j = 0; j < 4; j++) cpa16(dstK + j * 16, srcK + j * 8);
        cpa_commit();
    }

    for (int t = 0; t < 32; t++) {
        const int q0 = (2 * t + ks) * 32;
        const int q0n = (2 * (t < 31 ? t + 1 : t) + ks) * 32;  // clamped

        __syncthreads();   // PV(t-1) done: V, S, T buffers free

        // ---- issue cp.async: K(t+1) -> alt buf, V(t) ----
        {
            const __half* srcK = ksrc_base + (size_t)q0n * 32;
            const __half* srcV = vsrc_base + q0;
            uint32_t dstK = sb + (((t + 1) & 1) ? K1_OFF : K0_OFF) + tid * 80;
            uint32_t dstV = sb + V_OFF + tid * 80;
#pragma unroll
            for (int j = 0; j < 4; j++) {
                cpa16(dstK + j * 16, srcK + j * 8);
                cpa16(dstV + j * 16, srcV + j * 8);
            }
            cpa_commit();
        }

        // ---- mix C-init: bias at c-frag coords (overlaps cp.async) ----
        float cm[8][4];
#pragma unroll
        for (int j = 0; j < 8; j++) {
            int pl = 4 * w + (j >> 1), qh = j & 1;
            const float* bp =
                bias + ((size_t)(2 * lb) * Pc + p0 + pl) * Pc + q0 + 16 * qh + la;
            cm[j][0] = bp[0];
            cm[j][1] = bp[(size_t)Pc * Pc];
            cm[j][2] = bp[8];
            cm[j][3] = bp[(size_t)Pc * Pc + 8];
        }

        cpa_wait<1>();     // K(t) (prev group) complete
        __syncthreads();   // K(t) visible to all

        // ---- QK: S_h = Q_h @ K_h^T (warp = head) ----
        const char* kbuf = smem + ((t & 1) ? K1_OFF : K0_OFF);
#pragma unroll
        for (int nt = 0; nt < 4; nt++) {
            uint32_t bb[2][2];
#pragma unroll
            for (int k2 = 0; k2 < 2; k2++) {
                const char* kp = kbuf + (w * 32 + 8 * nt + la) * 80 + k2 * 32 + lb * 4;
                bb[k2][0] = *(const uint32_t*)(kp);
                bb[k2][1] = *(const uint32_t*)(kp + 16);
            }
#pragma unroll
            for (int mt = 0; mt < 2; mt++) {
                float cc[4] = {0.f, 0.f, 0.f, 0.f};
                mma16816h(cc, qf[mt][0], bb[0]);
                mma16816h(cc, qf[mt][1], bb[1]);
                char* s0 = smem + S_OFF + (16 * mt + la) * 516 + (8 * nt + 2 * lb) * 16 + w * 2;
                *(__half*)(s0)                = __float2half_rn(cc[0]);
                *(__half*)(s0 + 16)           = __float2half_rn(cc[1]);
                *(__half*)(s0 + 8 * 516)      = __float2half_rn(cc[2]);
                *(__half*)(s0 + 8 * 516 + 16) = __float2half_rn(cc[3]);
            }
        }
        __syncthreads();

        // ---- MIX: T[q][g] = S @ W^T + bias -> T fp16 ----
#pragma unroll
        for (int j = 0; j < 8; j++) {
            int pl = 4 * w + (j >> 1), qh = j & 1;
            const char* sp = smem + S_OFF + pl * 516 + (16 * qh + la) * 16 + lb * 4;
            uint32_t av[2];
            av[0] = *(const uint32_t*)(sp);
            av[1] = *(const uint32_t*)(sp + 128);
            mma16808h(cm[j], av, wfrag);
            char* t0 = smem + T_OFF + (2 * lb) * 2576 + pl * 80 + (16 * qh + la) * 2;
            *(__half*)(t0)             = __float2half_rn(cm[j][0]);
            *(__half*)(t0 + 2576)      = __float2half_rn(cm[j][1]);
            *(__half*)(t0 + 16)        = __float2half_rn(cm[j][2]);
            *(__half*)(t0 + 2576 + 16) = __float2half_rn(cm[j][3]);
        }
        cpa_wait<0>();     // V(t) complete (and K(t+1))
        __syncthreads();   // T + V visible

        // ---- PV: softmax in regs -> phi; single-pass fp16 P@V ----
        const char* tg = smem + T_OFF + w * 2576;
        uint32_t phi[2][2][4];
#pragma unroll
        for (int mt = 0; mt < 2; mt++) {
            const int rA = 16 * mt + la;
            float TA[8], TB[8];
#pragma unroll
            for (int kc = 0; kc < 2; kc++) {
                float2 u0 = __half22float2(
                    *(const __half2*)(tg + rA * 80 + (16 * kc + 2 * lb) * 2));
                float2 u1 = __half22float2(
                    *(const __half2*)(tg + rA * 80 + (16 * kc + 2 * lb + 8) * 2));
                float2 v0 = __half22float2(
                    *(const __half2*)(tg + (rA + 8) * 80 + (16 * kc + 2 * lb) * 2));
                float2 v1 = __half22float2(
                    *(const __half2*)(tg + (rA + 8) * 80 + (16 * kc + 2 * lb + 8) * 2));
                TA[4 * kc + 0] = u0.x; TA[4 * kc + 1] = u0.y;
                TA[4 * kc + 2] = u1.x; TA[4 * kc + 3] = u1.y;
                TB[4 * kc + 0] = v0.x; TB[4 * kc + 1] = v0.y;
                TB[4 * kc + 2] = v1.x; TB[4 * kc + 3] = v1.y;
            }
            float mxA = TA[0], mxB = TB[0];
#pragma unroll
            for (int i = 1; i < 8; i++) {
                mxA = fmaxf(mxA, TA[i]);
                mxB = fmaxf(mxB, TB[i]);
            }
            mxA = fmaxf(mxA, __shfl_xor_sync(0xffffffffu, mxA, 1));
            mxA = fmaxf(mxA, __shfl_xor_sync(0xffffffffu, mxA, 2));
            mxB = fmaxf(mxB, __shfl_xor_sync(0xffffffffu, mxB, 1));
            mxB = fmaxf(mxB, __shfl_xor_sync(0xffffffffu, mxB, 2));
            mxA = fmaxf(mxA, mr[mt][0]);
            mxB = fmaxf(mxB, mr[mt][1]);
            const float scA = __expf(mr[mt][0] - mxA);
            const float scB = __expf(mr[mt][1] - mxB);
            mr[mt][0] = mxA; mr[mt][1] = mxB;
            lr[mt][0] *= scA; lr[mt][1] *= scB;
#pragma unroll
            for (int nt = 0; nt < 4; nt++) {
                o[mt][nt][0] *= scA; o[mt][nt][1] *= scA;
                o[mt][nt][2] *= scB; o[mt][nt][3] *= scB;
            }
            float lsA = 0.f, lsB = 0.f;
#pragma unroll
            for (int i = 0; i < 8; i++) {
                TA[i] = __expf(TA[i] - mxA); lsA += TA[i];
                TB[i] = __expf(TB[i] - mxB); lsB += TB[i];
            }
            lr[mt][0] += lsA; lr[mt][1] += lsB;
#pragma unroll
            for (int kc = 0; kc < 2; kc++) {
                phi[mt][kc][0] = packh(TA[4 * kc + 0], TA[4 * kc + 1]);
                phi[mt][kc][1] = packh(TB[4 * kc + 0], TB[4 * kc + 1]);
                phi[mt][kc][2] = packh(TA[4 * kc + 2], TA[4 * kc + 3]);
                phi[mt][kc][3] = packh(TB[4 * kc + 2], TB[4 * kc + 3]);
            }
        }
#pragma unroll
        for (int kc = 0; kc < 2; kc++)
#pragma unroll
            for (int nt = 0; nt < 4; nt++) {
                const char* vp =
                    smem + V_OFF + (w * 32 + 8 * nt + la) * 80 + kc * 32 + lb * 4;
                uint32_t bh[2];
                bh[0] = *(const uint32_t*)(vp);
                bh[1] = *(const uint32_t*)(vp + 16);
                mma16816h(o[0][nt], phi[0][kc], bh);
                mma16816h(o[1][nt], phi[1][kc], bh);
            }
    }

    // ---- epilogue: write O partials + (m,l) to scratch ----
#pragma unroll
    for (int mt = 0; mt < 2; mt++) {
        float lA = lr[mt][0];
        lA += __shfl_xor_sync(0xffffffffu, lA, 1);
        lA += __shfl_xor_sync(0xffffffffu, lA, 2);
        float lB = lr[mt][1];
        lB += __shfl_xor_sync(0xffffffffu, lB, 1);
        lB += __shfl_xor_sync(0xffffffffu, lB, 2);
        const int rA = p0 + 16 * mt + la;
        float* obase = g_oscr + ((size_t)(ks * 2 + b) * Pc + rA) * 256 + w * 32 + 2 * lb;
#pragma unroll
        for (int nt = 0; nt < 4; nt++) {
            *(float2*)(obase + 8 * nt) = make_float2(o[mt][nt][0], o[mt][nt][1]);
            *(float2*)(obase + 8 * 256 + 8 * nt) = make_float2(o[mt][nt][2], o[mt][nt][3]);
        }
        if (lb == 0) {
            size_t mlb = ((size_t)(ks * 2 + b) * 8 + w) * Pc;
            g_mlscr[mlb + rA] = make_float2(mr[mt][0], lA);
            g_mlscr[mlb + rA + 8] = make_float2(mr[mt][1], lB);
        }
    }
}

// ---------------------------------------------------------------------------
// Key-split merge -> ctxt (fp16)
// ---------------------------------------------------------------------------
__global__ __launch_bounds__(256) void merge_k() {
    int idx = blockIdx.x * 256 + threadIdx.x;
    int c4 = idx & 63;
    int row = idx >> 6;                          // b*2048 + p
    int g = c4 >> 3;
    int b = row >> 11, p = row & 2047;
    float2 ml0 = g_mlscr[((size_t)(b * 8) + g) * Pc + p];
    float2 ml1 = g_mlscr[((size_t)((2 + b) * 8) + g) * Pc + p];
    float m = fmaxf(ml0.x, ml1.x);
    float e0 = __expf(ml0.x - m), e1 = __expf(ml1.x - m);
    float li = 1.0f / (e0 * ml0.y + e1 * ml1.y);
    e0 *= li; e1 *= li;
    const float4 a = *(const float4*)(g_oscr + (size_t)row * 256 + c4 * 4);
    const float4 c = *(const float4*)(g_oscr + (size_t)(Bc * Pc + row) * 256 + c4 * 4);
    __half2* dst = (__half2*)(g_ctxt_h + (size_t)row * 256 + c4 * 4);
    dst[0] = __floats2half2_rn(e0 * a.x + e1 * c.x, e0 * a.y + e1 * c.y);
    dst[1] = __floats2half2_rn(e0 * a.z + e1 * c.z, e0 * a.w + e1 * c.w);
}

// ---------------------------------------------------------------------------
extern "C" void kernel_launch(void* const* d_in, const int* in_sizes, int n_in,
                              void* d_out, int out_size) {
    (void)in_sizes; (void)n_in; (void)out_size;
    const float* x     = (const float*)d_in[0];
    const float* bias  = (const float*)d_in[1];
    const float* wqkv  = (const float*)d_in[2];
    const float* wtalk = (const float*)d_in[3];
    const float* wproj = (const float*)d_in[4];
    float* out = (float*)d_out;

    cudaFuncSetAttribute(attn_mma, cudaFuncAttributeMaxDynamicSharedMemorySize,
                         SM_ATTN);

    void* xh_ptr = nullptr;  cudaGetSymbolAddress(&xh_ptr, g_xh);
    void* wh_ptr = nullptr;  cudaGetSymbolAddress(&wh_ptr, g_wh);
    void* wp_ptr = nullptr;  cudaGetSymbolAddress(&wp_ptr, g_wp);

    // 0) convert x, Wqkv, Wproj to fp16
    cvt_f2h<<<(Bc * Pc * 128 / 4 + 255) / 256, 256>>>(x, (__half*)xh_ptr,
                                                      Bc * Pc * 128 / 4);
    cvt_f2h<<<(768 * 128 / 4 + 255) / 256, 256>>>(wqkv, (__half*)wh_ptr,
                                                  768 * 128 / 4);
    cvt_f2h<<<(128 * 256 / 4 + 255) / 256, 256>>>(wproj, (__half*)wp_ptr,
                                                  128 * 256 / 4);

    // 1) QKV projection (tensor pipe) + per-head fp16 scatter
    gemm_qkv_h<<<dim3(Bc * Pc / 128, 12), 256>>>();

    // 2) fused attention (pipelined cp.async, all-MMA) -> partials
    attn_mma<<<Bc * 2 * (Pc / 32), 256, SM_ATTN>>>(bias, wtalk);

    // 3) key-split merge -> ctxt fp16
    merge_k<<<1024, 256>>>();

    // 4) output projection (tensor pipe)
    gemm_proj<<<dim3(Bc * Pc / 128, 2), 256>>>(out);
}